// round 7
// baseline (speedup 1.0000x reference)
#include <cuda_runtime.h>
#include <cstdint>

#define N_NODES 50000
#define N_EDGES 600000
#define D_K     128
#define D_H1    128
#define D_H2    64

// ---------------- scratch (device globals: no allocation allowed) ----------
__device__ int   g_deg     [N_NODES];
__device__ float g_dinv    [N_NODES];
__device__ int   g_rowstart[N_NODES + 1];
__device__ int   g_cursor  [N_NODES];
__device__ int   g_csr_src [N_EDGES];
__device__ __align__(16) float g_t1  [N_NODES * D_H1];   // (x @ W1) * dinv[row]
__device__ __align__(16) float g_agg1[N_NODES * D_H1];   // aggregated layer-1
__device__ __align__(16) float g_t2  [N_NODES * D_H2];   // (relu(agg1+b1) @ W2) * dinv[row]

__device__ __forceinline__ int clampi(int v) {
    return min(max(v, 0), N_NODES - 1);
}

// ---------------- degree -----------------------------------------------------
__global__ void k_init_deg() {
    int i = blockIdx.x * blockDim.x + threadIdx.x;
    if (i < N_NODES) g_deg[i] = 1;          // self-loop
}

__global__ void k_count_deg(const int* __restrict__ ei) {
    int e = blockIdx.x * blockDim.x + threadIdx.x;
    if (e < N_EDGES) atomicAdd(&g_deg[clampi(ei[N_EDGES + e])], 1);  // dst
}

// ---------------- single-block scan: rowstart/cursor/dinv -------------------
__global__ void __launch_bounds__(1024) k_scan() {
    __shared__ int s[1024];
    const int T = 1024;
    const int C = (N_NODES + T - 1) / T;    // 49
    int t = threadIdx.x;
    int base = t * C;

    int sum = 0;
    for (int i = 0; i < C; i++) {
        int n = base + i;
        if (n < N_NODES) sum += g_deg[n] - 1;
    }
    s[t] = sum;
    __syncthreads();
    for (int off = 1; off < T; off <<= 1) {
        int add = (t >= off) ? s[t - off] : 0;
        __syncthreads();
        s[t] += add;
        __syncthreads();
    }
    int run = s[t] - sum;                   // exclusive prefix
    for (int i = 0; i < C; i++) {
        int n = base + i;
        if (n < N_NODES) {
            g_rowstart[n] = run;
            g_cursor[n]   = run;
            g_dinv[n]     = rsqrtf((float)g_deg[n]);
            run += g_deg[n] - 1;
        }
    }
    if (t == T - 1) g_rowstart[N_NODES] = run;   // == N_EDGES
}

// ---------------- CSR fill (src only) ---------------------------------------
__global__ void k_fill(const int* __restrict__ ei) {
    int e = blockIdx.x * blockDim.x + threadIdx.x;
    if (e >= N_EDGES) return;
    int src = clampi(ei[e]);
    int dst = clampi(ei[N_EDGES + e]);
    int pos = atomicAdd(&g_cursor[dst], 1);
    g_csr_src[pos] = src;
}

// ---------------- 8x8-tile SGEMM: T = (f(A) @ W) * dinv[row] ----------------
// Block tile: BM(=128) rows x BN cols. THREADS = (BM/8)*(BN/8).
// Each thread: 8x8 register tile. A staged transposed (As[k][row]) so the
// inner loop is 4x LDS.128 + 64 FFMA per k (1.0 B shared per FMA).
// If IN_TRANS: A elements pass through relu(a + b_in[k]) on load.
template<int BM, int BN, bool IN_TRANS>
__device__ __forceinline__ void gemm8x8_body(const float* __restrict__ A,
                                             const float* __restrict__ W,
                                             const float* __restrict__ b_in,
                                             float* __restrict__ T)
{
    constexpr int KC      = 32;
    constexpr int THREADS = (BM / 8) * (BN / 8);
    constexpr int TX      = BN / 8;          // col groups
    __shared__ float As[KC][BM];              // transposed A chunk
    __shared__ float Ws[KC][BN];

    const int tid  = threadIdx.x;
    const int tx   = tid % TX;
    const int ty   = tid / TX;
    const int row0 = blockIdx.x * BM;

    float acc[8][8];
#pragma unroll
    for (int i = 0; i < 8; i++)
#pragma unroll
        for (int j = 0; j < 8; j++) acc[i][j] = 0.f;

    for (int kc = 0; kc < D_K; kc += KC) {
        // ---- stage A chunk (BM x 32) transposed into As[k][row] -----------
        constexpr int AF4 = BM * KC / 4;      // float4 slots
#pragma unroll
        for (int q = 0; q < AF4 / THREADS; q++) {
            int f  = tid + q * THREADS;
            int r  = f >> 3;                  // row in tile (8 float4 per row)
            int k4 = f & 7;
            float4 v = make_float4(0.f, 0.f, 0.f, 0.f);
            int grow = row0 + r;
            if (grow < N_NODES)
                v = *(const float4*)&A[(size_t)grow * D_K + kc + k4 * 4];
            if constexpr (IN_TRANS) {
                float4 bb = *(const float4*)&b_in[kc + k4 * 4];
                v.x = fmaxf(v.x + bb.x, 0.f);
                v.y = fmaxf(v.y + bb.y, 0.f);
                v.z = fmaxf(v.z + bb.z, 0.f);
                v.w = fmaxf(v.w + bb.w, 0.f);
            }
            As[k4 * 4 + 0][r] = v.x;
            As[k4 * 4 + 1][r] = v.y;
            As[k4 * 4 + 2][r] = v.z;
            As[k4 * 4 + 3][r] = v.w;
        }
        // ---- stage W chunk (32 x BN), contiguous ---------------------------
        {
            const float4* Wg  = (const float4*)&W[(size_t)kc * BN];
            float4*       Wsp = (float4*)&Ws[0][0];
            constexpr int WF4 = KC * BN / 4;
#pragma unroll
            for (int q = 0; q < WF4 / THREADS; q++)
                Wsp[tid + q * THREADS] = Wg[tid + q * THREADS];
        }
        __syncthreads();

#pragma unroll
        for (int k = 0; k < KC; k++) {
            const float4* Ar = (const float4*)&As[k][0];
            const float4* Wr = (const float4*)&Ws[k][0];
            float4 a0 = Ar[ty * 2 + 0];
            float4 a1 = Ar[ty * 2 + 1];
            float4 w0 = Wr[tx * 2 + 0];
            float4 w1 = Wr[tx * 2 + 1];
            float av[8] = {a0.x, a0.y, a0.z, a0.w, a1.x, a1.y, a1.z, a1.w};
            float wv[8] = {w0.x, w0.y, w0.z, w0.w, w1.x, w1.y, w1.z, w1.w};
#pragma unroll
            for (int i = 0; i < 8; i++)
#pragma unroll
                for (int j = 0; j < 8; j++)
                    acc[i][j] = fmaf(av[i], wv[j], acc[i][j]);
        }
        __syncthreads();
    }

    // ---- epilogue: prescale by dinv[row], store --------------------------
#pragma unroll
    for (int i = 0; i < 8; i++) {
        int r = row0 + ty * 8 + i;
        if (r >= N_NODES) continue;
        float dv = g_dinv[r];
        float4 t0 = make_float4(acc[i][0] * dv, acc[i][1] * dv,
                                acc[i][2] * dv, acc[i][3] * dv);
        float4 t1 = make_float4(acc[i][4] * dv, acc[i][5] * dv,
                                acc[i][6] * dv, acc[i][7] * dv);
        *(float4*)&T[(size_t)r * BN + tx * 8 + 0] = t0;
        *(float4*)&T[(size_t)r * BN + tx * 8 + 4] = t1;
    }
}

__global__ void __launch_bounds__(256)
k_gemm1(const float* __restrict__ x, const float* __restrict__ W1) {
    gemm8x8_body<128, 128, false>(x, W1, nullptr, g_t1);
}

__global__ void __launch_bounds__(128)
k_gemm2(const float* __restrict__ W2, const float* __restrict__ b1) {
    gemm8x8_body<128, 64, true>(g_agg1, W2, b1, g_t2);
}

// ---------------- layer-1 aggregate: gather, warp per node ------------------
// agg1[n] = dinv[n] * ( t1'[n] + sum_{e: dst=n} t1'[src_e] )
__global__ void k_agg1() {
    int n    = (blockIdx.x * blockDim.x + threadIdx.x) >> 5;
    int lane = threadIdx.x & 31;
    if (n >= N_NODES) return;

    int   s0 = g_rowstart[n];
    int   s1 = g_rowstart[n + 1];
    float dv = g_dinv[n];

    float4 acc = *(const float4*)&g_t1[(size_t)n * D_H1 + lane * 4];

    int e = s0;
    for (; e + 1 < s1; e += 2) {
        int srcA = g_csr_src[e];
        int srcB = g_csr_src[e + 1];
        float4 vA = *(const float4*)&g_t1[(size_t)srcA * D_H1 + lane * 4];
        float4 vB = *(const float4*)&g_t1[(size_t)srcB * D_H1 + lane * 4];
        acc.x += vA.x + vB.x;
        acc.y += vA.y + vB.y;
        acc.z += vA.z + vB.z;
        acc.w += vA.w + vB.w;
    }
    if (e < s1) {
        int src = g_csr_src[e];
        float4 v = *(const float4*)&g_t1[(size_t)src * D_H1 + lane * 4];
        acc.x += v.x; acc.y += v.y; acc.z += v.z; acc.w += v.w;
    }
    acc.x *= dv; acc.y *= dv; acc.z *= dv; acc.w *= dv;
    *(float4*)&g_agg1[(size_t)n * D_H1 + lane * 4] = acc;
}

// ---------------- layer-2 aggregate fused with final GEMV -------------------
__global__ void k_agg2_final(const float* __restrict__ b2,
                             const float* __restrict__ W3,
                             const float* __restrict__ b3,
                             float* __restrict__ out)
{
    int n    = (blockIdx.x * blockDim.x + threadIdx.x) >> 5;
    int lane = threadIdx.x & 31;
    if (n >= N_NODES) return;

    int   s0 = g_rowstart[n];
    int   s1 = g_rowstart[n + 1];
    float dv = g_dinv[n];

    float2 acc = *(const float2*)&g_t2[(size_t)n * D_H2 + lane * 2];

    int e = s0;
    for (; e + 1 < s1; e += 2) {
        int srcA = g_csr_src[e];
        int srcB = g_csr_src[e + 1];
        float2 vA = *(const float2*)&g_t2[(size_t)srcA * D_H2 + lane * 2];
        float2 vB = *(const float2*)&g_t2[(size_t)srcB * D_H2 + lane * 2];
        acc.x += vA.x + vB.x;
        acc.y += vA.y + vB.y;
    }
    if (e < s1) {
        int src = g_csr_src[e];
        float2 v = *(const float2*)&g_t2[(size_t)src * D_H2 + lane * 2];
        acc.x += v.x; acc.y += v.y;
    }
    acc.x *= dv; acc.y *= dv;

    float2 bb = *(const float2*)&b2[lane * 2];
    float2 w  = *(const float2*)&W3[lane * 2];
    float h0 = fmaxf(acc.x + bb.x, 0.f);
    float h1 = fmaxf(acc.y + bb.y, 0.f);
    float s  = fmaf(h0, w.x, h1 * w.y);
#pragma unroll
    for (int o = 16; o; o >>= 1) s += __shfl_xor_sync(0xffffffffu, s, o);
    if (lane == 0) out[n] = s + b3[0];
}

// ---------------- launch (single stream) ------------------------------------
extern "C" void kernel_launch(void* const* d_in, const int* in_sizes, int n_in,
                              void* d_out, int out_size)
{
    const float* x  = (const float*)d_in[0];
    const int*   ei = (const int*)d_in[1];     // int32 edge_index
    const float* W1 = (const float*)d_in[2];
    const float* b1 = (const float*)d_in[3];
    const float* W2 = (const float*)d_in[4];
    const float* b2 = (const float*)d_in[5];
    const float* W3 = (const float*)d_in[6];
    const float* b3 = (const float*)d_in[7];
    float*       out = (float*)d_out;
    (void)in_sizes; (void)n_in; (void)out_size;

    k_init_deg <<<(N_NODES + 255) / 256, 256>>>();
    k_count_deg<<<(N_EDGES + 255) / 256, 256>>>(ei);
    k_scan     <<<1, 1024>>>();
    k_fill     <<<(N_EDGES + 255) / 256, 256>>>(ei);

    k_gemm1<<<(N_NODES + 127) / 128, 256>>>(x, W1);
    k_agg1 <<<(N_NODES * 32 + 255) / 256, 256>>>();

    k_gemm2<<<(N_NODES + 127) / 128, 128>>>(W2, b1);
    k_agg2_final<<<(N_NODES * 32 + 255) / 256, 256>>>(b2, W3, b3, out);
}